// round 7
// baseline (speedup 1.0000x reference)
#include <cuda_runtime.h>

#define C 32
#define BMAX 16
#define EPS 1e-5f

// Scratch (device globals: no allocation allowed in kernel_launch)
__device__ float g_sum[BMAX * C];
__device__ float g_sq[BMAX * C];
__device__ float g_cnt[BMAX];
__device__ float g_scale[BMAX * C];
__device__ float g_shift[BMAX * C];

// ---------------------------------------------------------------------------
// Kernel 0: zero the accumulators (must run every graph replay)
// ---------------------------------------------------------------------------
__global__ void zero_stats_kernel() {
    int i = threadIdx.x;
    if (i < BMAX * C) { g_sum[i] = 0.0f; g_sq[i] = 0.0f; }
    if (i < BMAX) g_cnt[i] = 0.0f;
}

// ---------------------------------------------------------------------------
// Kernel 1: per-segment sum / sumsq / count.
// One warp owns a contiguous chunk of rows. batch_id is sorted, so if
// first==last batch in the chunk we take a float4 streaming fast path:
// lane L loads the float4 at column (L&7), row offset (L>>3) -> a warp
// consumes 4 rows per LDG.128. Main loop keeps 4 independent LDG.128 in
// flight per thread (16 rows/warp/iter) so per-SM in-flight bytes exceed
// the DRAM latency-bandwidth product with ~2.5x slack.
// ---------------------------------------------------------------------------
__global__ void __launch_bounds__(256, 4)
reduce_kernel(const float* __restrict__ data,
              const int* __restrict__ bid,
              int N, int rows_per_warp) {
    int warp = (int)((blockIdx.x * blockDim.x + threadIdx.x) >> 5);
    int lane = threadIdx.x & 31;

    int r0 = warp * rows_per_warp;
    if (r0 >= N) return;
    int r1 = r0 + rows_per_warp;
    if (r1 > N) r1 = N;

    int b_first = bid[r0];
    int b_last = bid[r1 - 1];

    if (b_first == b_last) {
        // ---- Fast path: single segment, 4 LDG.128 in flight ----
        const float4* p4 = reinterpret_cast<const float4*>(
            data + (size_t)r0 * C);
        int rows = r1 - r0;
        int sub = lane & 7;        // which float4 column (channels sub*4..+3)
        int rg  = lane >> 3;       // row offset within 4-row group

        float4 s0 = make_float4(0.f, 0.f, 0.f, 0.f);
        float4 q0 = make_float4(0.f, 0.f, 0.f, 0.f);
        float4 s1 = make_float4(0.f, 0.f, 0.f, 0.f);
        float4 q1 = make_float4(0.f, 0.f, 0.f, 0.f);

        const float4* base = p4 + (size_t)rg * 8 + sub;
        int r = 0;
        for (; r + 16 <= rows; r += 16) {
            // 4 independent loads issued before any arithmetic.
            float4 a = __ldcs(base + (size_t)(r +  0) * 8);
            float4 b = __ldcs(base + (size_t)(r +  4) * 8);
            float4 c = __ldcs(base + (size_t)(r +  8) * 8);
            float4 d = __ldcs(base + (size_t)(r + 12) * 8);
            s0.x += a.x; s0.y += a.y; s0.z += a.z; s0.w += a.w;
            q0.x = fmaf(a.x, a.x, q0.x); q0.y = fmaf(a.y, a.y, q0.y);
            q0.z = fmaf(a.z, a.z, q0.z); q0.w = fmaf(a.w, a.w, q0.w);
            s1.x += b.x; s1.y += b.y; s1.z += b.z; s1.w += b.w;
            q1.x = fmaf(b.x, b.x, q1.x); q1.y = fmaf(b.y, b.y, q1.y);
            q1.z = fmaf(b.z, b.z, q1.z); q1.w = fmaf(b.w, b.w, q1.w);
            s0.x += c.x; s0.y += c.y; s0.z += c.z; s0.w += c.w;
            q0.x = fmaf(c.x, c.x, q0.x); q0.y = fmaf(c.y, c.y, q0.y);
            q0.z = fmaf(c.z, c.z, q0.z); q0.w = fmaf(c.w, c.w, q0.w);
            s1.x += d.x; s1.y += d.y; s1.z += d.z; s1.w += d.w;
            q1.x = fmaf(d.x, d.x, q1.x); q1.y = fmaf(d.y, d.y, q1.y);
            q1.z = fmaf(d.z, d.z, q1.z); q1.w = fmaf(d.w, d.w, q1.w);
        }
        for (; r + 4 <= rows; r += 4) {
            float4 a = __ldcs(base + (size_t)r * 8);
            s0.x += a.x; s0.y += a.y; s0.z += a.z; s0.w += a.w;
            q0.x = fmaf(a.x, a.x, q0.x); q0.y = fmaf(a.y, a.y, q0.y);
            q0.z = fmaf(a.z, a.z, q0.z); q0.w = fmaf(a.w, a.w, q0.w);
        }
        if (r < rows && r + rg < rows) {   // 1-3 remaining rows, predicated
            float4 a = __ldcs(base + (size_t)r * 8);
            s0.x += a.x; s0.y += a.y; s0.z += a.z; s0.w += a.w;
            q0.x = fmaf(a.x, a.x, q0.x); q0.y = fmaf(a.y, a.y, q0.y);
            q0.z = fmaf(a.z, a.z, q0.z); q0.w = fmaf(a.w, a.w, q0.w);
        }

        s0.x += s1.x; s0.y += s1.y; s0.z += s1.z; s0.w += s1.w;
        q0.x += q1.x; q0.y += q1.y; q0.z += q1.z; q0.w += q1.w;

        // Combine lanes sharing the same channels (rg = 0..3): xor 16, 8.
        #pragma unroll
        for (int off = 16; off >= 8; off >>= 1) {
            s0.x += __shfl_xor_sync(0xffffffffu, s0.x, off);
            s0.y += __shfl_xor_sync(0xffffffffu, s0.y, off);
            s0.z += __shfl_xor_sync(0xffffffffu, s0.z, off);
            s0.w += __shfl_xor_sync(0xffffffffu, s0.w, off);
            q0.x += __shfl_xor_sync(0xffffffffu, q0.x, off);
            q0.y += __shfl_xor_sync(0xffffffffu, q0.y, off);
            q0.z += __shfl_xor_sync(0xffffffffu, q0.z, off);
            q0.w += __shfl_xor_sync(0xffffffffu, q0.w, off);
        }

        if (rg == 0) {   // lanes 0..7 flush channels sub*4 .. sub*4+3
            int b4 = b_first * C + sub * 4;
            atomicAdd(&g_sum[b4 + 0], s0.x);
            atomicAdd(&g_sum[b4 + 1], s0.y);
            atomicAdd(&g_sum[b4 + 2], s0.z);
            atomicAdd(&g_sum[b4 + 3], s0.w);
            atomicAdd(&g_sq[b4 + 0], q0.x);
            atomicAdd(&g_sq[b4 + 1], q0.y);
            atomicAdd(&g_sq[b4 + 2], q0.z);
            atomicAdd(&g_sq[b4 + 3], q0.w);
        }
        if (lane == 0) atomicAdd(&g_cnt[b_first], (float)rows);
    } else {
        // ---- Slow path: chunk crosses a segment boundary (<=15 warps) ----
        int cur = b_first;
        float s = 0.0f, q = 0.0f, cnt = 0.0f;
        for (int r = r0; r < r1; ++r) {
            int b = bid[r];
            if (b != cur) {
                atomicAdd(&g_sum[cur * C + lane], s);
                atomicAdd(&g_sq[cur * C + lane], q);
                if (lane == 0) atomicAdd(&g_cnt[cur], cnt);
                s = 0.0f; q = 0.0f; cnt = 0.0f; cur = b;
            }
            float x = data[(size_t)r * C + lane];
            s += x; q = fmaf(x, x, q); cnt += 1.0f;
        }
        atomicAdd(&g_sum[cur * C + lane], s);
        atomicAdd(&g_sq[cur * C + lane], q);
        if (lane == 0) atomicAdd(&g_cnt[cur], cnt);
    }
}

// ---------------------------------------------------------------------------
// Kernel 2: fold stats into per-(b,c) scale/shift.
// out = (x - mean) * inv_std * w + bias  ==  x*scale + shift
// ---------------------------------------------------------------------------
__global__ void finalize_kernel(const float* __restrict__ w,
                                const float* __restrict__ bias) {
    int i = threadIdx.x;           // 0..BMAX*C-1
    if (i >= BMAX * C) return;
    int b = i / C, c = i % C;
    float cnt = g_cnt[b];
    float norm = 1.0f / (cnt + EPS);
    float sum = g_sum[i];
    float mean = sum * norm;
    float var = (g_sq[i] - 2.0f * mean * sum + mean * mean * cnt) * norm;
    float inv_std = rsqrtf(var + EPS);
    float wc = w ? w[c] : 1.0f;
    float bc = bias ? bias[c] : 0.0f;
    float sc = inv_std * wc;
    g_scale[i] = sc;
    g_shift[i] = bc - mean * sc;
}

// ---------------------------------------------------------------------------
// Kernel 3: normalize. 4 consecutive float4 per thread (64B). The 4 float4s
// never cross a row boundary (4t mod 8 in {0,4}), so one bid load covers all
// four. Streaming hints keep the 512MB of data/out from thrashing L2.
// (Measured 5.97 TB/s effective — at the LTS ceiling; unchanged.)
// ---------------------------------------------------------------------------
__global__ void normalize_kernel(const float4* __restrict__ data4,
                                 const int* __restrict__ bid,
                                 float4* __restrict__ out4, int n4) {
    __shared__ float4 s_scale[BMAX * C / 4];
    __shared__ float4 s_shift[BMAX * C / 4];
    for (int i = threadIdx.x; i < BMAX * C / 4; i += blockDim.x) {
        s_scale[i] = reinterpret_cast<const float4*>(g_scale)[i];
        s_shift[i] = reinterpret_cast<const float4*>(g_shift)[i];
    }
    __syncthreads();

    int t = blockIdx.x * blockDim.x + threadIdx.x;
    int i = t * 4;
    if (i >= n4) return;

    int row = i >> 3;
    int b = bid[row];
    int qb = (b << 3) | (i & 7);   // (i&7) in {0,4}; qb..qb+3 same row

    if (i + 3 < n4) {
        float4 d0 = __ldcs(&data4[i + 0]);
        float4 d1 = __ldcs(&data4[i + 1]);
        float4 d2 = __ldcs(&data4[i + 2]);
        float4 d3 = __ldcs(&data4[i + 3]);
        float4 c0 = s_scale[qb + 0], h0 = s_shift[qb + 0];
        float4 c1 = s_scale[qb + 1], h1 = s_shift[qb + 1];
        float4 c2 = s_scale[qb + 2], h2 = s_shift[qb + 2];
        float4 c3 = s_scale[qb + 3], h3 = s_shift[qb + 3];
        float4 o0, o1, o2, o3;
        o0.x = fmaf(d0.x, c0.x, h0.x); o0.y = fmaf(d0.y, c0.y, h0.y);
        o0.z = fmaf(d0.z, c0.z, h0.z); o0.w = fmaf(d0.w, c0.w, h0.w);
        o1.x = fmaf(d1.x, c1.x, h1.x); o1.y = fmaf(d1.y, c1.y, h1.y);
        o1.z = fmaf(d1.z, c1.z, h1.z); o1.w = fmaf(d1.w, c1.w, h1.w);
        o2.x = fmaf(d2.x, c2.x, h2.x); o2.y = fmaf(d2.y, c2.y, h2.y);
        o2.z = fmaf(d2.z, c2.z, h2.z); o2.w = fmaf(d2.w, c2.w, h2.w);
        o3.x = fmaf(d3.x, c3.x, h3.x); o3.y = fmaf(d3.y, c3.y, h3.y);
        o3.z = fmaf(d3.z, c3.z, h3.z); o3.w = fmaf(d3.w, c3.w, h3.w);
        __stcs(&out4[i + 0], o0);
        __stcs(&out4[i + 1], o1);
        __stcs(&out4[i + 2], o2);
        __stcs(&out4[i + 3], o3);
    } else {
        for (int k = 0; k < 4 && i + k < n4; ++k) {
            float4 d = __ldcs(&data4[i + k]);
            float4 c = s_scale[qb + k], h = s_shift[qb + k];
            float4 o;
            o.x = fmaf(d.x, c.x, h.x); o.y = fmaf(d.y, c.y, h.y);
            o.z = fmaf(d.z, c.z, h.z); o.w = fmaf(d.w, c.w, h.w);
            __stcs(&out4[i + k], o);
        }
    }
}

// ---------------------------------------------------------------------------
extern "C" void kernel_launch(void* const* d_in, const int* in_sizes, int n_in,
                              void* d_out, int out_size) {
    const float* data = (const float*)d_in[0];
    const int* bid = (const int*)d_in[1];
    int N = in_sizes[0] / C;

    // Locate weights/bias among the remaining inputs (size-32 fp32 arrays).
    const float* w = nullptr;
    const float* bias = nullptr;
    for (int i = 2; i < n_in; ++i) {
        if (in_sizes[i] == C) {
            if (!w) w = (const float*)d_in[i];
            else if (!bias) bias = (const float*)d_in[i];
        }
    }

    zero_stats_kernel<<<1, BMAX * C>>>();

    const int threads = 256;
    const int blocks = 148 * 8;                 // 9472 warps
    int warps = blocks * (threads / 32);
    int rpw = (N + warps - 1) / warps;
    reduce_kernel<<<blocks, threads>>>(data, bid, N, rpw);

    finalize_kernel<<<1, BMAX * C>>>(w, bias);

    int n4 = N * (C / 4);
    int nthreads_total = (n4 + 3) / 4;
    int nblocks = (nthreads_total + threads - 1) / threads;
    normalize_kernel<<<nblocks, threads>>>((const float4*)data, bid,
                                           (float4*)d_out, n4);
}

// round 8
// speedup vs baseline: 1.4314x; 1.4314x over previous
#include <cuda_runtime.h>

#define C 32
#define BMAX 16
#define EPS 1e-5f

// Scratch (device globals: no allocation allowed in kernel_launch)
__device__ float g_sum[BMAX * C];
__device__ float g_sq[BMAX * C];
__device__ float g_cnt[BMAX];
__device__ float g_scale[BMAX * C];
__device__ float g_shift[BMAX * C];

// ---------------------------------------------------------------------------
// Kernel 0: zero the accumulators (must run every graph replay)
// ---------------------------------------------------------------------------
__global__ void zero_stats_kernel() {
    int i = threadIdx.x;
    if (i < BMAX * C) { g_sum[i] = 0.0f; g_sq[i] = 0.0f; }
    if (i < BMAX) g_cnt[i] = 0.0f;
}

// ---------------------------------------------------------------------------
// Warp-cooperative accumulation of one single-segment run [rs, re).
// Lane L loads the float4 at column (L&7), row offset (L>>3): a warp
// consumes 4 rows per LDG.128 round, 2 loads in flight, then a cross-lane
// xor-shuffle combine and one atomic flush per (lane<8, stat).
// ---------------------------------------------------------------------------
__device__ __forceinline__ void accum_run(const float* __restrict__ data,
                                          int rs, int re, int b, int lane) {
    int rows = re - rs;
    if (rows <= 0) return;
    int sub = lane & 7;        // float4 column (channels sub*4 .. sub*4+3)
    int rg  = lane >> 3;       // row offset within 4-row group

    const float4* base = reinterpret_cast<const float4*>(
        data + (size_t)rs * C) + (size_t)rg * 8 + sub;

    float4 s0 = make_float4(0.f, 0.f, 0.f, 0.f);
    float4 q0 = make_float4(0.f, 0.f, 0.f, 0.f);
    float4 s1 = make_float4(0.f, 0.f, 0.f, 0.f);
    float4 q1 = make_float4(0.f, 0.f, 0.f, 0.f);

    int r = 0;
    for (; r + 8 <= rows; r += 8) {
        float4 a = base[(size_t)r * 8];
        float4 c = base[(size_t)(r + 4) * 8];
        s0.x += a.x; s0.y += a.y; s0.z += a.z; s0.w += a.w;
        q0.x = fmaf(a.x, a.x, q0.x); q0.y = fmaf(a.y, a.y, q0.y);
        q0.z = fmaf(a.z, a.z, q0.z); q0.w = fmaf(a.w, a.w, q0.w);
        s1.x += c.x; s1.y += c.y; s1.z += c.z; s1.w += c.w;
        q1.x = fmaf(c.x, c.x, q1.x); q1.y = fmaf(c.y, c.y, q1.y);
        q1.z = fmaf(c.z, c.z, q1.z); q1.w = fmaf(c.w, c.w, q1.w);
    }
    if (r + 4 <= rows) {
        float4 a = base[(size_t)r * 8];
        s0.x += a.x; s0.y += a.y; s0.z += a.z; s0.w += a.w;
        q0.x = fmaf(a.x, a.x, q0.x); q0.y = fmaf(a.y, a.y, q0.y);
        q0.z = fmaf(a.z, a.z, q0.z); q0.w = fmaf(a.w, a.w, q0.w);
        r += 4;
    }
    if (r < rows && r + rg < rows) {   // 1-3 remaining rows, predicated
        float4 a = base[(size_t)r * 8];
        s0.x += a.x; s0.y += a.y; s0.z += a.z; s0.w += a.w;
        q0.x = fmaf(a.x, a.x, q0.x); q0.y = fmaf(a.y, a.y, q0.y);
        q0.z = fmaf(a.z, a.z, q0.z); q0.w = fmaf(a.w, a.w, q0.w);
    }

    s0.x += s1.x; s0.y += s1.y; s0.z += s1.z; s0.w += s1.w;
    q0.x += q1.x; q0.y += q1.y; q0.z += q1.z; q0.w += q1.w;

    // Combine lanes sharing the same channels (rg = 0..3): xor 16, 8.
    #pragma unroll
    for (int off = 16; off >= 8; off >>= 1) {
        s0.x += __shfl_xor_sync(0xffffffffu, s0.x, off);
        s0.y += __shfl_xor_sync(0xffffffffu, s0.y, off);
        s0.z += __shfl_xor_sync(0xffffffffu, s0.z, off);
        s0.w += __shfl_xor_sync(0xffffffffu, s0.w, off);
        q0.x += __shfl_xor_sync(0xffffffffu, q0.x, off);
        q0.y += __shfl_xor_sync(0xffffffffu, q0.y, off);
        q0.z += __shfl_xor_sync(0xffffffffu, q0.z, off);
        q0.w += __shfl_xor_sync(0xffffffffu, q0.w, off);
    }

    if (rg == 0) {   // lanes 0..7 flush channels sub*4 .. sub*4+3
        int b4 = b * C + sub * 4;
        atomicAdd(&g_sum[b4 + 0], s0.x);
        atomicAdd(&g_sum[b4 + 1], s0.y);
        atomicAdd(&g_sum[b4 + 2], s0.z);
        atomicAdd(&g_sum[b4 + 3], s0.w);
        atomicAdd(&g_sq[b4 + 0], q0.x);
        atomicAdd(&g_sq[b4 + 1], q0.y);
        atomicAdd(&g_sq[b4 + 2], q0.z);
        atomicAdd(&g_sq[b4 + 3], q0.w);
    }
    if (lane == 0) atomicAdd(&g_cnt[b], (float)rows);
}

// ---------------------------------------------------------------------------
// Kernel 1: per-segment sum / sumsq / count.
// One warp owns a contiguous row chunk. batch_id is sorted: single-segment
// chunks go straight to accum_run; boundary chunks (<=15 warps) binary-
// search each run boundary (<=16 runs, ~8 broadcast loads per search) and
// feed every run through the SAME streaming accumulator — no serial
// per-row path anywhere.
// ---------------------------------------------------------------------------
__global__ void reduce_kernel(const float* __restrict__ data,
                              const int* __restrict__ bid,
                              int N, int rows_per_warp) {
    int warp = (int)((blockIdx.x * blockDim.x + threadIdx.x) >> 5);
    int lane = threadIdx.x & 31;

    int r0 = warp * rows_per_warp;
    if (r0 >= N) return;
    int r1 = r0 + rows_per_warp;
    if (r1 > N) r1 = N;

    int b_first = bid[r0];
    int b_last = bid[r1 - 1];

    if (b_first == b_last) {
        accum_run(data, r0, r1, b_first, lane);
    } else {
        int r = r0;
        int b = b_first;
        while (r < r1) {
            // Binary search for the end of the run of value b in [r, r1).
            int lo = r + 1, hi = r1;
            while (lo < hi) {
                int mid = (lo + hi) >> 1;     // same addr across lanes:
                if (bid[mid] == b) lo = mid + 1;  // broadcast load
                else hi = mid;
            }
            accum_run(data, r, lo, b, lane);
            r = lo;
            if (r < r1) b = bid[r];
        }
    }
}

// ---------------------------------------------------------------------------
// Kernel 2: fold stats into per-(b,c) scale/shift.
// out = (x - mean) * inv_std * w + bias  ==  x*scale + shift
// ---------------------------------------------------------------------------
__global__ void finalize_kernel(const float* __restrict__ w,
                                const float* __restrict__ bias) {
    int i = threadIdx.x;           // 0..BMAX*C-1
    if (i >= BMAX * C) return;
    int b = i / C, c = i % C;
    float cnt = g_cnt[b];
    float norm = 1.0f / (cnt + EPS);
    float sum = g_sum[i];
    float mean = sum * norm;
    float var = (g_sq[i] - 2.0f * mean * sum + mean * mean * cnt) * norm;
    float inv_std = rsqrtf(var + EPS);
    float wc = w ? w[c] : 1.0f;
    float bc = bias ? bias[c] : 0.0f;
    float sc = inv_std * wc;
    g_scale[i] = sc;
    g_shift[i] = bc - mean * sc;
}

// ---------------------------------------------------------------------------
// Kernel 3: normalize. 4 consecutive float4 per thread (64B). Measured at
// 6.0 TB/s effective (~95% of LTS ceiling) — unchanged from R6.
// ---------------------------------------------------------------------------
__global__ void normalize_kernel(const float4* __restrict__ data4,
                                 const int* __restrict__ bid,
                                 float4* __restrict__ out4, int n4) {
    __shared__ float4 s_scale[BMAX * C / 4];
    __shared__ float4 s_shift[BMAX * C / 4];
    for (int i = threadIdx.x; i < BMAX * C / 4; i += blockDim.x) {
        s_scale[i] = reinterpret_cast<const float4*>(g_scale)[i];
        s_shift[i] = reinterpret_cast<const float4*>(g_shift)[i];
    }
    __syncthreads();

    int t = blockIdx.x * blockDim.x + threadIdx.x;
    int i = t * 4;
    if (i >= n4) return;

    int row = i >> 3;
    int b = bid[row];
    int qb = (b << 3) | (i & 7);   // (i&7) in {0,4}; qb..qb+3 same row

    if (i + 3 < n4) {
        float4 d0 = __ldcs(&data4[i + 0]);
        float4 d1 = __ldcs(&data4[i + 1]);
        float4 d2 = __ldcs(&data4[i + 2]);
        float4 d3 = __ldcs(&data4[i + 3]);
        float4 c0 = s_scale[qb + 0], h0 = s_shift[qb + 0];
        float4 c1 = s_scale[qb + 1], h1 = s_shift[qb + 1];
        float4 c2 = s_scale[qb + 2], h2 = s_shift[qb + 2];
        float4 c3 = s_scale[qb + 3], h3 = s_shift[qb + 3];
        float4 o0, o1, o2, o3;
        o0.x = fmaf(d0.x, c0.x, h0.x); o0.y = fmaf(d0.y, c0.y, h0.y);
        o0.z = fmaf(d0.z, c0.z, h0.z); o0.w = fmaf(d0.w, c0.w, h0.w);
        o1.x = fmaf(d1.x, c1.x, h1.x); o1.y = fmaf(d1.y, c1.y, h1.y);
        o1.z = fmaf(d1.z, c1.z, h1.z); o1.w = fmaf(d1.w, c1.w, h1.w);
        o2.x = fmaf(d2.x, c2.x, h2.x); o2.y = fmaf(d2.y, c2.y, h2.y);
        o2.z = fmaf(d2.z, c2.z, h2.z); o2.w = fmaf(d2.w, c2.w, h2.w);
        o3.x = fmaf(d3.x, c3.x, h3.x); o3.y = fmaf(d3.y, c3.y, h3.y);
        o3.z = fmaf(d3.z, c3.z, h3.z); o3.w = fmaf(d3.w, c3.w, h3.w);
        __stcs(&out4[i + 0], o0);
        __stcs(&out4[i + 1], o1);
        __stcs(&out4[i + 2], o2);
        __stcs(&out4[i + 3], o3);
    } else {
        for (int k = 0; k < 4 && i + k < n4; ++k) {
            float4 d = __ldcs(&data4[i + k]);
            float4 c = s_scale[qb + k], h = s_shift[qb + k];
            float4 o;
            o.x = fmaf(d.x, c.x, h.x); o.y = fmaf(d.y, c.y, h.y);
            o.z = fmaf(d.z, c.z, h.z); o.w = fmaf(d.w, c.w, h.w);
            __stcs(&out4[i + k], o);
        }
    }
}

// ---------------------------------------------------------------------------
extern "C" void kernel_launch(void* const* d_in, const int* in_sizes, int n_in,
                              void* d_out, int out_size) {
    const float* data = (const float*)d_in[0];
    const int* bid = (const int*)d_in[1];
    int N = in_sizes[0] / C;

    // Locate weights/bias among the remaining inputs (size-32 fp32 arrays).
    const float* w = nullptr;
    const float* bias = nullptr;
    for (int i = 2; i < n_in; ++i) {
        if (in_sizes[i] == C) {
            if (!w) w = (const float*)d_in[i];
            else if (!bias) bias = (const float*)d_in[i];
        }
    }

    zero_stats_kernel<<<1, BMAX * C>>>();

    const int threads = 256;
    const int blocks = 148 * 8;                 // 9472 warps
    int warps = blocks * (threads / 32);
    int rpw = (N + warps - 1) / warps;
    reduce_kernel<<<blocks, threads>>>(data, bid, N, rpw);

    finalize_kernel<<<1, BMAX * C>>>(w, bias);

    int n4 = N * (C / 4);
    int nthreads_total = (n4 + 3) / 4;
    int nblocks = (nthreads_total + threads - 1) / threads;
    normalize_kernel<<<nblocks, threads>>>((const float4*)data, bid,
                                           (float4*)d_out, n4);
}

// round 9
// speedup vs baseline: 1.6645x; 1.1628x over previous
#include <cuda_runtime.h>

#define C 32
#define BMAX 16
#define EPS 1e-5f

// Scratch (device globals: no allocation allowed in kernel_launch)
__device__ float g_sum[BMAX * C];
__device__ float g_sq[BMAX * C];
__device__ float g_cnt[BMAX];
__device__ float g_scale[BMAX * C];
__device__ float g_shift[BMAX * C];

// ---------------------------------------------------------------------------
// Kernel 0: zero the accumulators (must run every graph replay)
// ---------------------------------------------------------------------------
__global__ void zero_stats_kernel() {
    int i = threadIdx.x;
    if (i < BMAX * C) { g_sum[i] = 0.0f; g_sq[i] = 0.0f; }
    if (i < BMAX) g_cnt[i] = 0.0f;
}

// ---------------------------------------------------------------------------
// Warp-cooperative accumulation of one single-segment run [rs, re).
// Lane L loads the float4 at column (L&7), row offset (L>>3): a warp
// consumes 4 rows per LDG.128. The 8-row main loop is software-pipelined
// with one-chunk lookahead: chunk k+1's two loads issue BEFORE chunk k's
// data is consumed, so each warp keeps ~4 LDG.128 in flight instead of 2
// (in-order issue otherwise serializes on the first FADD's scoreboard).
// ---------------------------------------------------------------------------
__device__ __forceinline__ void accum_run(const float* __restrict__ data,
                                          int rs, int re, int b, int lane) {
    int rows = re - rs;
    if (rows <= 0) return;
    int sub = lane & 7;        // float4 column (channels sub*4 .. sub*4+3)
    int rg  = lane >> 3;       // row offset within 4-row group

    const float4* base = reinterpret_cast<const float4*>(
        data + (size_t)rs * C) + (size_t)rg * 8 + sub;

    float4 s = make_float4(0.f, 0.f, 0.f, 0.f);
    float4 q = make_float4(0.f, 0.f, 0.f, 0.f);

    int nch = rows >> 3;               // full 8-row chunks
    int r = nch << 3;
    if (nch > 0) {
        float4 a = base[0];
        float4 c = base[32];
        for (int k = 1; k < nch; ++k) {
            const float4* p = base + (size_t)k * 64;
            float4 a2 = p[0];          // prefetch chunk k
            float4 c2 = p[32];
            s.x += a.x; s.y += a.y; s.z += a.z; s.w += a.w;
            q.x = fmaf(a.x, a.x, q.x); q.y = fmaf(a.y, a.y, q.y);
            q.z = fmaf(a.z, a.z, q.z); q.w = fmaf(a.w, a.w, q.w);
            s.x += c.x; s.y += c.y; s.z += c.z; s.w += c.w;
            q.x = fmaf(c.x, c.x, q.x); q.y = fmaf(c.y, c.y, q.y);
            q.z = fmaf(c.z, c.z, q.z); q.w = fmaf(c.w, c.w, q.w);
            a = a2; c = c2;
        }
        s.x += a.x; s.y += a.y; s.z += a.z; s.w += a.w;
        q.x = fmaf(a.x, a.x, q.x); q.y = fmaf(a.y, a.y, q.y);
        q.z = fmaf(a.z, a.z, q.z); q.w = fmaf(a.w, a.w, q.w);
        s.x += c.x; s.y += c.y; s.z += c.z; s.w += c.w;
        q.x = fmaf(c.x, c.x, q.x); q.y = fmaf(c.y, c.y, q.y);
        q.z = fmaf(c.z, c.z, q.z); q.w = fmaf(c.w, c.w, q.w);
    }
    if (r + 4 <= rows) {
        float4 a = base[(size_t)r * 8];
        s.x += a.x; s.y += a.y; s.z += a.z; s.w += a.w;
        q.x = fmaf(a.x, a.x, q.x); q.y = fmaf(a.y, a.y, q.y);
        q.z = fmaf(a.z, a.z, q.z); q.w = fmaf(a.w, a.w, q.w);
        r += 4;
    }
    if (r < rows && r + rg < rows) {   // 1-3 remaining rows, predicated
        float4 a = base[(size_t)r * 8];
        s.x += a.x; s.y += a.y; s.z += a.z; s.w += a.w;
        q.x = fmaf(a.x, a.x, q.x); q.y = fmaf(a.y, a.y, q.y);
        q.z = fmaf(a.z, a.z, q.z); q.w = fmaf(a.w, a.w, q.w);
    }

    // Combine lanes sharing the same channels (rg = 0..3): xor 16, 8.
    #pragma unroll
    for (int off = 16; off >= 8; off >>= 1) {
        s.x += __shfl_xor_sync(0xffffffffu, s.x, off);
        s.y += __shfl_xor_sync(0xffffffffu, s.y, off);
        s.z += __shfl_xor_sync(0xffffffffu, s.z, off);
        s.w += __shfl_xor_sync(0xffffffffu, s.w, off);
        q.x += __shfl_xor_sync(0xffffffffu, q.x, off);
        q.y += __shfl_xor_sync(0xffffffffu, q.y, off);
        q.z += __shfl_xor_sync(0xffffffffu, q.z, off);
        q.w += __shfl_xor_sync(0xffffffffu, q.w, off);
    }

    if (rg == 0) {   // lanes 0..7 flush channels sub*4 .. sub*4+3
        int b4 = b * C + sub * 4;
        atomicAdd(&g_sum[b4 + 0], s.x);
        atomicAdd(&g_sum[b4 + 1], s.y);
        atomicAdd(&g_sum[b4 + 2], s.z);
        atomicAdd(&g_sum[b4 + 3], s.w);
        atomicAdd(&g_sq[b4 + 0], q.x);
        atomicAdd(&g_sq[b4 + 1], q.y);
        atomicAdd(&g_sq[b4 + 2], q.z);
        atomicAdd(&g_sq[b4 + 3], q.w);
    }
    if (lane == 0) atomicAdd(&g_cnt[b], (float)rows);
}

// ---------------------------------------------------------------------------
// Kernel 1: per-segment sum / sumsq / count.
// One warp owns a contiguous row chunk. batch_id is sorted: single-segment
// chunks go straight to accum_run; boundary chunks (<=15 warps) binary-
// search each run boundary (<=16 runs, ~9 broadcast loads per search) and
// feed every run through the SAME streaming accumulator.
// ---------------------------------------------------------------------------
__global__ void reduce_kernel(const float* __restrict__ data,
                              const int* __restrict__ bid,
                              int N, int rows_per_warp) {
    int warp = (int)((blockIdx.x * blockDim.x + threadIdx.x) >> 5);
    int lane = threadIdx.x & 31;

    int r0 = warp * rows_per_warp;
    if (r0 >= N) return;
    int r1 = r0 + rows_per_warp;
    if (r1 > N) r1 = N;

    int b_first = bid[r0];
    int b_last = bid[r1 - 1];

    if (b_first == b_last) {
        accum_run(data, r0, r1, b_first, lane);
    } else {
        int r = r0;
        int b = b_first;
        while (r < r1) {
            // Binary search for the end of the run of value b in [r, r1).
            int lo = r + 1, hi = r1;
            while (lo < hi) {
                int mid = (lo + hi) >> 1;         // broadcast load
                if (bid[mid] == b) lo = mid + 1;
                else hi = mid;
            }
            accum_run(data, r, lo, b, lane);
            r = lo;
            if (r < r1) b = bid[r];
        }
    }
}

// ---------------------------------------------------------------------------
// Kernel 2: fold stats into per-(b,c) scale/shift.
// out = (x - mean) * inv_std * w + bias  ==  x*scale + shift
// ---------------------------------------------------------------------------
__global__ void finalize_kernel(const float* __restrict__ w,
                                const float* __restrict__ bias) {
    int i = threadIdx.x;           // 0..BMAX*C-1
    if (i >= BMAX * C) return;
    int b = i / C, c = i % C;
    float cnt = g_cnt[b];
    float norm = 1.0f / (cnt + EPS);
    float sum = g_sum[i];
    float mean = sum * norm;
    float var = (g_sq[i] - 2.0f * mean * sum + mean * mean * cnt) * norm;
    float inv_std = rsqrtf(var + EPS);
    float wc = w ? w[c] : 1.0f;
    float bc = bias ? bias[c] : 0.0f;
    float sc = inv_std * wc;
    g_scale[i] = sc;
    g_shift[i] = bc - mean * sc;
}

// ---------------------------------------------------------------------------
// Kernel 3: normalize. 4 consecutive float4 per thread (64B). Measured at
// 6.0 TB/s effective (~95% of LTS ceiling) — unchanged.
// ---------------------------------------------------------------------------
__global__ void normalize_kernel(const float4* __restrict__ data4,
                                 const int* __restrict__ bid,
                                 float4* __restrict__ out4, int n4) {
    __shared__ float4 s_scale[BMAX * C / 4];
    __shared__ float4 s_shift[BMAX * C / 4];
    for (int i = threadIdx.x; i < BMAX * C / 4; i += blockDim.x) {
        s_scale[i] = reinterpret_cast<const float4*>(g_scale)[i];
        s_shift[i] = reinterpret_cast<const float4*>(g_shift)[i];
    }
    __syncthreads();

    int t = blockIdx.x * blockDim.x + threadIdx.x;
    int i = t * 4;
    if (i >= n4) return;

    int row = i >> 3;
    int b = bid[row];
    int qb = (b << 3) | (i & 7);   // (i&7) in {0,4}; qb..qb+3 same row

    if (i + 3 < n4) {
        float4 d0 = __ldcs(&data4[i + 0]);
        float4 d1 = __ldcs(&data4[i + 1]);
        float4 d2 = __ldcs(&data4[i + 2]);
        float4 d3 = __ldcs(&data4[i + 3]);
        float4 c0 = s_scale[qb + 0], h0 = s_shift[qb + 0];
        float4 c1 = s_scale[qb + 1], h1 = s_shift[qb + 1];
        float4 c2 = s_scale[qb + 2], h2 = s_shift[qb + 2];
        float4 c3 = s_scale[qb + 3], h3 = s_shift[qb + 3];
        float4 o0, o1, o2, o3;
        o0.x = fmaf(d0.x, c0.x, h0.x); o0.y = fmaf(d0.y, c0.y, h0.y);
        o0.z = fmaf(d0.z, c0.z, h0.z); o0.w = fmaf(d0.w, c0.w, h0.w);
        o1.x = fmaf(d1.x, c1.x, h1.x); o1.y = fmaf(d1.y, c1.y, h1.y);
        o1.z = fmaf(d1.z, c1.z, h1.z); o1.w = fmaf(d1.w, c1.w, h1.w);
        o2.x = fmaf(d2.x, c2.x, h2.x); o2.y = fmaf(d2.y, c2.y, h2.y);
        o2.z = fmaf(d2.z, c2.z, h2.z); o2.w = fmaf(d2.w, c2.w, h2.w);
        o3.x = fmaf(d3.x, c3.x, h3.x); o3.y = fmaf(d3.y, c3.y, h3.y);
        o3.z = fmaf(d3.z, c3.z, h3.z); o3.w = fmaf(d3.w, c3.w, h3.w);
        __stcs(&out4[i + 0], o0);
        __stcs(&out4[i + 1], o1);
        __stcs(&out4[i + 2], o2);
        __stcs(&out4[i + 3], o3);
    } else {
        for (int k = 0; k < 4 && i + k < n4; ++k) {
            float4 d = __ldcs(&data4[i + k]);
            float4 c = s_scale[qb + k], h = s_shift[qb + k];
            float4 o;
            o.x = fmaf(d.x, c.x, h.x); o.y = fmaf(d.y, c.y, h.y);
            o.z = fmaf(d.z, c.z, h.z); o.w = fmaf(d.w, c.w, h.w);
            __stcs(&out4[i + k], o);
        }
    }
}

// ---------------------------------------------------------------------------
extern "C" void kernel_launch(void* const* d_in, const int* in_sizes, int n_in,
                              void* d_out, int out_size) {
    const float* data = (const float*)d_in[0];
    const int* bid = (const int*)d_in[1];
    int N = in_sizes[0] / C;

    // Locate weights/bias among the remaining inputs (size-32 fp32 arrays).
    const float* w = nullptr;
    const float* bias = nullptr;
    for (int i = 2; i < n_in; ++i) {
        if (in_sizes[i] == C) {
            if (!w) w = (const float*)d_in[i];
            else if (!bias) bias = (const float*)d_in[i];
        }
    }

    zero_stats_kernel<<<1, BMAX * C>>>();

    const int threads = 256;
    const int blocks = 148 * 4;                 // single wave, 4736 warps
    int warps = blocks * (threads / 32);
    int rpw = (N + warps - 1) / warps;
    reduce_kernel<<<blocks, threads>>>(data, bid, N, rpw);

    finalize_kernel<<<1, BMAX * C>>>(w, bias);

    int n4 = N * (C / 4);
    int nthreads_total = (n4 + 3) / 4;
    int nblocks = (nthreads_total + threads - 1) / threads;
    normalize_kernel<<<nblocks, threads>>>((const float4*)data, bid,
                                           (float4*)d_out, n4);
}

// round 10
// speedup vs baseline: 1.7687x; 1.0626x over previous
#include <cuda_runtime.h>

#define C 32
#define BMAX 16
#define EPS 1e-5f

// Scratch (device globals: no allocation allowed in kernel_launch)
__device__ float g_sum[BMAX * C];
__device__ float g_sq[BMAX * C];
__device__ float g_cnt[BMAX];
__device__ float g_scale[BMAX * C];
__device__ float g_shift[BMAX * C];

// ---------------------------------------------------------------------------
// Kernel 0: zero the accumulators (must run every graph replay)
// ---------------------------------------------------------------------------
__global__ void zero_stats_kernel() {
    int i = threadIdx.x;
    if (i < BMAX * C) { g_sum[i] = 0.0f; g_sq[i] = 0.0f; }
    if (i < BMAX) g_cnt[i] = 0.0f;
}

// ---------------------------------------------------------------------------
// Warp-cooperative accumulation of one single-segment run [rs, re).
// Lane L loads the float4 at column (L&7), row offset (L>>3): a warp
// consumes 4 rows per LDG.128. 8-row main loop with one-chunk lookahead
// (~4 LDG.128 in flight per warp).  [R9: measured ~5.1 TB/s — keep as-is]
// ---------------------------------------------------------------------------
__device__ __forceinline__ void accum_run(const float* __restrict__ data,
                                          int rs, int re, int b, int lane) {
    int rows = re - rs;
    if (rows <= 0) return;
    int sub = lane & 7;        // float4 column (channels sub*4 .. sub*4+3)
    int rg  = lane >> 3;       // row offset within 4-row group

    const float4* base = reinterpret_cast<const float4*>(
        data + (size_t)rs * C) + (size_t)rg * 8 + sub;

    float4 s = make_float4(0.f, 0.f, 0.f, 0.f);
    float4 q = make_float4(0.f, 0.f, 0.f, 0.f);

    int nch = rows >> 3;               // full 8-row chunks
    int r = nch << 3;
    if (nch > 0) {
        float4 a = base[0];
        float4 c = base[32];
        for (int k = 1; k < nch; ++k) {
            const float4* p = base + (size_t)k * 64;
            float4 a2 = p[0];          // prefetch chunk k
            float4 c2 = p[32];
            s.x += a.x; s.y += a.y; s.z += a.z; s.w += a.w;
            q.x = fmaf(a.x, a.x, q.x); q.y = fmaf(a.y, a.y, q.y);
            q.z = fmaf(a.z, a.z, q.z); q.w = fmaf(a.w, a.w, q.w);
            s.x += c.x; s.y += c.y; s.z += c.z; s.w += c.w;
            q.x = fmaf(c.x, c.x, q.x); q.y = fmaf(c.y, c.y, q.y);
            q.z = fmaf(c.z, c.z, q.z); q.w = fmaf(c.w, c.w, q.w);
            a = a2; c = c2;
        }
        s.x += a.x; s.y += a.y; s.z += a.z; s.w += a.w;
        q.x = fmaf(a.x, a.x, q.x); q.y = fmaf(a.y, a.y, q.y);
        q.z = fmaf(a.z, a.z, q.z); q.w = fmaf(a.w, a.w, q.w);
        s.x += c.x; s.y += c.y; s.z += c.z; s.w += c.w;
        q.x = fmaf(c.x, c.x, q.x); q.y = fmaf(c.y, c.y, q.y);
        q.z = fmaf(c.z, c.z, q.z); q.w = fmaf(c.w, c.w, q.w);
    }
    if (r + 4 <= rows) {
        float4 a = base[(size_t)r * 8];
        s.x += a.x; s.y += a.y; s.z += a.z; s.w += a.w;
        q.x = fmaf(a.x, a.x, q.x); q.y = fmaf(a.y, a.y, q.y);
        q.z = fmaf(a.z, a.z, q.z); q.w = fmaf(a.w, a.w, q.w);
        r += 4;
    }
    if (r < rows && r + rg < rows) {   // 1-3 remaining rows, predicated
        float4 a = base[(size_t)r * 8];
        s.x += a.x; s.y += a.y; s.z += a.z; s.w += a.w;
        q.x = fmaf(a.x, a.x, q.x); q.y = fmaf(a.y, a.y, q.y);
        q.z = fmaf(a.z, a.z, q.z); q.w = fmaf(a.w, a.w, q.w);
    }

    // Combine lanes sharing the same channels (rg = 0..3): xor 16, 8.
    #pragma unroll
    for (int off = 16; off >= 8; off >>= 1) {
        s.x += __shfl_xor_sync(0xffffffffu, s.x, off);
        s.y += __shfl_xor_sync(0xffffffffu, s.y, off);
        s.z += __shfl_xor_sync(0xffffffffu, s.z, off);
        s.w += __shfl_xor_sync(0xffffffffu, s.w, off);
        q.x += __shfl_xor_sync(0xffffffffu, q.x, off);
        q.y += __shfl_xor_sync(0xffffffffu, q.y, off);
        q.z += __shfl_xor_sync(0xffffffffu, q.z, off);
        q.w += __shfl_xor_sync(0xffffffffu, q.w, off);
    }

    if (rg == 0) {   // lanes 0..7 flush channels sub*4 .. sub*4+3
        int b4 = b * C + sub * 4;
        atomicAdd(&g_sum[b4 + 0], s.x);
        atomicAdd(&g_sum[b4 + 1], s.y);
        atomicAdd(&g_sum[b4 + 2], s.z);
        atomicAdd(&g_sum[b4 + 3], s.w);
        atomicAdd(&g_sq[b4 + 0], q.x);
        atomicAdd(&g_sq[b4 + 1], q.y);
        atomicAdd(&g_sq[b4 + 2], q.z);
        atomicAdd(&g_sq[b4 + 3], q.w);
    }
    if (lane == 0) atomicAdd(&g_cnt[b], (float)rows);
}

// ---------------------------------------------------------------------------
// Kernel 1: per-segment sum / sumsq / count.
// ---------------------------------------------------------------------------
__global__ void reduce_kernel(const float* __restrict__ data,
                              const int* __restrict__ bid,
                              int N, int rows_per_warp) {
    int warp = (int)((blockIdx.x * blockDim.x + threadIdx.x) >> 5);
    int lane = threadIdx.x & 31;

    int r0 = warp * rows_per_warp;
    if (r0 >= N) return;
    int r1 = r0 + rows_per_warp;
    if (r1 > N) r1 = N;

    int b_first = bid[r0];
    int b_last = bid[r1 - 1];

    if (b_first == b_last) {
        accum_run(data, r0, r1, b_first, lane);
    } else {
        int r = r0;
        int b = b_first;
        while (r < r1) {
            int lo = r + 1, hi = r1;
            while (lo < hi) {                 // binary search run end
                int mid = (lo + hi) >> 1;     // broadcast load
                if (bid[mid] == b) lo = mid + 1;
                else hi = mid;
            }
            accum_run(data, r, lo, b, lane);
            r = lo;
            if (r < r1) b = bid[r];
        }
    }
}

// ---------------------------------------------------------------------------
// Kernel 2: fold stats into per-(b,c) scale/shift.
// ---------------------------------------------------------------------------
__global__ void finalize_kernel(const float* __restrict__ w,
                                const float* __restrict__ bias) {
    int i = threadIdx.x;           // 0..BMAX*C-1
    if (i >= BMAX * C) return;
    int b = i / C, c = i % C;
    float cnt = g_cnt[b];
    float norm = 1.0f / (cnt + EPS);
    float sum = g_sum[i];
    float mean = sum * norm;
    float var = (g_sq[i] - 2.0f * mean * sum + mean * mean * cnt) * norm;
    float inv_std = rsqrtf(var + EPS);
    float wc = w ? w[c] : 1.0f;
    float bc = bias ? bias[c] : 0.0f;
    float sc = inv_std * wc;
    g_scale[i] = sc;
    g_shift[i] = bc - mean * sc;
}

// ---------------------------------------------------------------------------
// Normalize one single-segment run [rs, re): scale/shift live in REGISTERS
// (loaded once per run from smem), so the inner loop is pure
// LDG.128 -> FMA -> STG.128 with one-chunk load lookahead. This removes the
// 8 per-element LDS.128 that made the old normalize L1tex-bound (L1=84%).
// ---------------------------------------------------------------------------
__device__ __forceinline__ void norm_run(const float* __restrict__ data,
                                         float* __restrict__ out,
                                         const float4* s_scale,
                                         const float4* s_shift,
                                         int rs, int re, int b, int lane) {
    int rows = re - rs;
    if (rows <= 0) return;
    int sub = lane & 7;
    int rg  = lane >> 3;

    float4 sc = s_scale[b * 8 + sub];   // once per run
    float4 sh = s_shift[b * 8 + sub];

    const float4* pi = reinterpret_cast<const float4*>(
        data + (size_t)rs * C) + (size_t)rg * 8 + sub;
    float4* po = reinterpret_cast<float4*>(
        out + (size_t)rs * C) + (size_t)rg * 8 + sub;

    int nch = rows >> 3;               // full 8-row chunks
    int r = nch << 3;
    if (nch > 0) {
        float4 a = __ldcs(pi);
        float4 c = __ldcs(pi + 32);
        for (int k = 1; k < nch; ++k) {
            const float4* p = pi + (size_t)k * 64;
            float4 a2 = __ldcs(p);         // prefetch chunk k
            float4 c2 = __ldcs(p + 32);
            float4 o0, o1;
            o0.x = fmaf(a.x, sc.x, sh.x); o0.y = fmaf(a.y, sc.y, sh.y);
            o0.z = fmaf(a.z, sc.z, sh.z); o0.w = fmaf(a.w, sc.w, sh.w);
            o1.x = fmaf(c.x, sc.x, sh.x); o1.y = fmaf(c.y, sc.y, sh.y);
            o1.z = fmaf(c.z, sc.z, sh.z); o1.w = fmaf(c.w, sc.w, sh.w);
            float4* po_k = po + (size_t)(k - 1) * 64;
            __stcs(po_k, o0);
            __stcs(po_k + 32, o1);
            a = a2; c = c2;
        }
        float4 o0, o1;
        o0.x = fmaf(a.x, sc.x, sh.x); o0.y = fmaf(a.y, sc.y, sh.y);
        o0.z = fmaf(a.z, sc.z, sh.z); o0.w = fmaf(a.w, sc.w, sh.w);
        o1.x = fmaf(c.x, sc.x, sh.x); o1.y = fmaf(c.y, sc.y, sh.y);
        o1.z = fmaf(c.z, sc.z, sh.z); o1.w = fmaf(c.w, sc.w, sh.w);
        float4* po_k = po + (size_t)(nch - 1) * 64;
        __stcs(po_k, o0);
        __stcs(po_k + 32, o1);
    }
    if (r + 4 <= rows) {
        float4 a = __ldcs(pi + (size_t)r * 8);
        float4 o;
        o.x = fmaf(a.x, sc.x, sh.x); o.y = fmaf(a.y, sc.y, sh.y);
        o.z = fmaf(a.z, sc.z, sh.z); o.w = fmaf(a.w, sc.w, sh.w);
        __stcs(po + (size_t)r * 8, o);
        r += 4;
    }
    if (r < rows && r + rg < rows) {   // 1-3 remaining rows, predicated
        float4 a = __ldcs(pi + (size_t)r * 8);
        float4 o;
        o.x = fmaf(a.x, sc.x, sh.x); o.y = fmaf(a.y, sc.y, sh.y);
        o.z = fmaf(a.z, sc.z, sh.z); o.w = fmaf(a.w, sc.w, sh.w);
        __stcs(po + (size_t)r * 8, o);
    }
}

// ---------------------------------------------------------------------------
// Kernel 3: normalize, warp-chunked like the reduce. Single-segment chunks
// hit norm_run directly; boundary chunks binary-search their <=16 runs.
// ---------------------------------------------------------------------------
__global__ void normalize_kernel(const float* __restrict__ data,
                                 const int* __restrict__ bid,
                                 float* __restrict__ out,
                                 int N, int rows_per_warp) {
    __shared__ float4 s_scale[BMAX * C / 4];
    __shared__ float4 s_shift[BMAX * C / 4];
    for (int i = threadIdx.x; i < BMAX * C / 4; i += blockDim.x) {
        s_scale[i] = reinterpret_cast<const float4*>(g_scale)[i];
        s_shift[i] = reinterpret_cast<const float4*>(g_shift)[i];
    }
    __syncthreads();

    int warp = (int)((blockIdx.x * blockDim.x + threadIdx.x) >> 5);
    int lane = threadIdx.x & 31;

    int r0 = warp * rows_per_warp;
    if (r0 >= N) return;
    int r1 = r0 + rows_per_warp;
    if (r1 > N) r1 = N;

    int b_first = bid[r0];
    int b_last = bid[r1 - 1];

    if (b_first == b_last) {
        norm_run(data, out, s_scale, s_shift, r0, r1, b_first, lane);
    } else {
        int r = r0;
        int b = b_first;
        while (r < r1) {
            int lo = r + 1, hi = r1;
            while (lo < hi) {
                int mid = (lo + hi) >> 1;     // broadcast load
                if (bid[mid] == b) lo = mid + 1;
                else hi = mid;
            }
            norm_run(data, out, s_scale, s_shift, r, lo, b, lane);
            r = lo;
            if (r < r1) b = bid[r];
        }
    }
}

// ---------------------------------------------------------------------------
extern "C" void kernel_launch(void* const* d_in, const int* in_sizes, int n_in,
                              void* d_out, int out_size) {
    const float* data = (const float*)d_in[0];
    const int* bid = (const int*)d_in[1];
    int N = in_sizes[0] / C;

    // Locate weights/bias among the remaining inputs (size-32 fp32 arrays).
    const float* w = nullptr;
    const float* bias = nullptr;
    for (int i = 2; i < n_in; ++i) {
        if (in_sizes[i] == C) {
            if (!w) w = (const float*)d_in[i];
            else if (!bias) bias = (const float*)d_in[i];
        }
    }

    zero_stats_kernel<<<1, BMAX * C>>>();

    const int threads = 256;

    // Reduce: single wave at 4 blocks/SM (R9-validated config).
    {
        const int blocks = 148 * 4;
        int warps = blocks * (threads / 32);
        int rpw = (N + warps - 1) / warps;
        reduce_kernel<<<blocks, threads>>>(data, bid, N, rpw);
    }

    finalize_kernel<<<1, BMAX * C>>>(w, bias);

    // Normalize: single wave at 8 blocks/SM (load+store needs more warps).
    {
        const int blocks = 148 * 8;
        int warps = blocks * (threads / 32);
        int rpw = (N + warps - 1) / warps;
        normalize_kernel<<<blocks, threads>>>(data, bid, (float*)d_out,
                                              N, rpw);
    }
}

// round 11
// speedup vs baseline: 1.7724x; 1.0021x over previous
#include <cuda_runtime.h>

#define C 32
#define BMAX 16
#define EPS 1e-5f

// Scratch (device globals: zero-initialized at module load; finalize_kernel
// resets them after consuming, so every graph replay starts clean).
__device__ float g_sum[BMAX * C];
__device__ float g_sq[BMAX * C];
__device__ float g_cnt[BMAX];
__device__ float g_scale[BMAX * C];
__device__ float g_shift[BMAX * C];

// ---------------------------------------------------------------------------
// Warp-cooperative accumulation of one single-segment run [rs, re).
// Lane L loads the float4 at column (L&7), row offset (L>>3): a warp
// consumes 4 rows per LDG.128. 16-row main loop with one-iteration
// lookahead: 4 LDG.128 prefetched while 4 are consumed (~8 in flight).
// ---------------------------------------------------------------------------
__device__ __forceinline__ void accum_run(const float* __restrict__ data,
                                          int rs, int re, int b, int lane) {
    int rows = re - rs;
    if (rows <= 0) return;
    int sub = lane & 7;        // float4 column (channels sub*4 .. sub*4+3)
    int rg  = lane >> 3;       // row offset within 4-row group

    const float4* base = reinterpret_cast<const float4*>(
        data + (size_t)rs * C) + (size_t)rg * 8 + sub;

    float4 s = make_float4(0.f, 0.f, 0.f, 0.f);
    float4 q = make_float4(0.f, 0.f, 0.f, 0.f);

    #define ACC(v)                                                   \
        s.x += (v).x; s.y += (v).y; s.z += (v).z; s.w += (v).w;      \
        q.x = fmaf((v).x, (v).x, q.x); q.y = fmaf((v).y, (v).y, q.y);\
        q.z = fmaf((v).z, (v).z, q.z); q.w = fmaf((v).w, (v).w, q.w)

    int nch = rows >> 4;               // full 16-row chunks
    int r = nch << 4;
    if (nch > 0) {
        float4 a0 = base[0];
        float4 a1 = base[32];
        float4 a2 = base[64];
        float4 a3 = base[96];
        for (int k = 1; k < nch; ++k) {
            const float4* p = base + (size_t)k * 128;
            float4 b0 = p[0];          // prefetch chunk k (4 loads batched)
            float4 b1 = p[32];
            float4 b2 = p[64];
            float4 b3 = p[96];
            ACC(a0); ACC(a1); ACC(a2); ACC(a3);
            a0 = b0; a1 = b1; a2 = b2; a3 = b3;
        }
        ACC(a0); ACC(a1); ACC(a2); ACC(a3);
    }
    for (; r + 4 <= rows; r += 4) {    // 0-3 remaining 4-row groups
        float4 a = base[(size_t)r * 8];
        ACC(a);
    }
    if (r < rows && r + rg < rows) {   // 1-3 remaining rows, predicated
        float4 a = base[(size_t)r * 8];
        ACC(a);
    }
    #undef ACC

    // Combine lanes sharing the same channels (rg = 0..3): xor 16, 8.
    #pragma unroll
    for (int off = 16; off >= 8; off >>= 1) {
        s.x += __shfl_xor_sync(0xffffffffu, s.x, off);
        s.y += __shfl_xor_sync(0xffffffffu, s.y, off);
        s.z += __shfl_xor_sync(0xffffffffu, s.z, off);
        s.w += __shfl_xor_sync(0xffffffffu, s.w, off);
        q.x += __shfl_xor_sync(0xffffffffu, q.x, off);
        q.y += __shfl_xor_sync(0xffffffffu, q.y, off);
        q.z += __shfl_xor_sync(0xffffffffu, q.z, off);
        q.w += __shfl_xor_sync(0xffffffffu, q.w, off);
    }

    if (rg == 0) {   // lanes 0..7 flush channels sub*4 .. sub*4+3
        int b4 = b * C + sub * 4;
        atomicAdd(&g_sum[b4 + 0], s.x);
        atomicAdd(&g_sum[b4 + 1], s.y);
        atomicAdd(&g_sum[b4 + 2], s.z);
        atomicAdd(&g_sum[b4 + 3], s.w);
        atomicAdd(&g_sq[b4 + 0], q.x);
        atomicAdd(&g_sq[b4 + 1], q.y);
        atomicAdd(&g_sq[b4 + 2], q.z);
        atomicAdd(&g_sq[b4 + 3], q.w);
    }
    if (lane == 0) atomicAdd(&g_cnt[b], (float)rows);
}

// ---------------------------------------------------------------------------
// Kernel 1: per-segment sum / sumsq / count.
// Single-segment chunks stream directly; boundary chunks (<=15 warps)
// binary-search each run boundary and reuse the streaming accumulator.
// ---------------------------------------------------------------------------
__global__ void reduce_kernel(const float* __restrict__ data,
                              const int* __restrict__ bid,
                              int N, int rows_per_warp) {
    int warp = (int)((blockIdx.x * blockDim.x + threadIdx.x) >> 5);
    int lane = threadIdx.x & 31;

    int r0 = warp * rows_per_warp;
    if (r0 >= N) return;
    int r1 = r0 + rows_per_warp;
    if (r1 > N) r1 = N;

    int b_first = bid[r0];
    int b_last = bid[r1 - 1];

    if (b_first == b_last) {
        accum_run(data, r0, r1, b_first, lane);
    } else {
        int r = r0;
        int b = b_first;
        while (r < r1) {
            int lo = r + 1, hi = r1;
            while (lo < hi) {                 // binary search run end
                int mid = (lo + hi) >> 1;     // broadcast load
                if (bid[mid] == b) lo = mid + 1;
                else hi = mid;
            }
            accum_run(data, r, lo, b, lane);
            r = lo;
            if (r < r1) b = bid[r];
        }
    }
}

// ---------------------------------------------------------------------------
// Kernel 2: fold stats into per-(b,c) scale/shift, THEN reset the
// accumulators to zero so the next graph replay starts clean (this replaces
// the separate zero_stats launch).
// ---------------------------------------------------------------------------
__global__ void finalize_kernel(const float* __restrict__ w,
                                const float* __restrict__ bias) {
    int i = threadIdx.x;           // 0..BMAX*C-1
    if (i >= BMAX * C) return;
    int b = i / C, c = i % C;
    float cnt = g_cnt[b];
    float norm = 1.0f / (cnt + EPS);
    float sum = g_sum[i];
    float mean = sum * norm;
    float var = (g_sq[i] - 2.0f * mean * sum + mean * mean * cnt) * norm;
    float inv_std = rsqrtf(var + EPS);
    float wc = w ? w[c] : 1.0f;
    float bc = bias ? bias[c] : 0.0f;
    float sc = inv_std * wc;
    g_scale[i] = sc;
    g_shift[i] = bc - mean * sc;
    // Consume-and-reset for the next replay.
    g_sum[i] = 0.0f;
    g_sq[i] = 0.0f;
    if (c == 0) g_cnt[b] = 0.0f;
}

// ---------------------------------------------------------------------------
// Normalize one single-segment run [rs, re): scale/shift in registers
// (loaded once per run), inner loop pure LDG.128 -> FMA -> STG.128 with
// one-chunk lookahead.  [R10: 6.4 TB/s effective — at ceiling, unchanged]
// ---------------------------------------------------------------------------
__device__ __forceinline__ void norm_run(const float* __restrict__ data,
                                         float* __restrict__ out,
                                         const float4* s_scale,
                                         const float4* s_shift,
                                         int rs, int re, int b, int lane) {
    int rows = re - rs;
    if (rows <= 0) return;
    int sub = lane & 7;
    int rg  = lane >> 3;

    float4 sc = s_scale[b * 8 + sub];   // once per run
    float4 sh = s_shift[b * 8 + sub];

    const float4* pi = reinterpret_cast<const float4*>(
        data + (size_t)rs * C) + (size_t)rg * 8 + sub;
    float4* po = reinterpret_cast<float4*>(
        out + (size_t)rs * C) + (size_t)rg * 8 + sub;

    int nch = rows >> 3;               // full 8-row chunks
    int r = nch << 3;
    if (nch > 0) {
        float4 a = __ldcs(pi);
        float4 c = __ldcs(pi + 32);
        for (int k = 1; k < nch; ++k) {
            const float4* p = pi + (size_t)k * 64;
            float4 a2 = __ldcs(p);         // prefetch chunk k
            float4 c2 = __ldcs(p + 32);
            float4 o0, o1;
            o0.x = fmaf(a.x, sc.x, sh.x); o0.y = fmaf(a.y, sc.y, sh.y);
            o0.z = fmaf(a.z, sc.z, sh.z); o0.w = fmaf(a.w, sc.w, sh.w);
            o1.x = fmaf(c.x, sc.x, sh.x); o1.y = fmaf(c.y, sc.y, sh.y);
            o1.z = fmaf(c.z, sc.z, sh.z); o1.w = fmaf(c.w, sc.w, sh.w);
            float4* po_k = po + (size_t)(k - 1) * 64;
            __stcs(po_k, o0);
            __stcs(po_k + 32, o1);
            a = a2; c = c2;
        }
        float4 o0, o1;
        o0.x = fmaf(a.x, sc.x, sh.x); o0.y = fmaf(a.y, sc.y, sh.y);
        o0.z = fmaf(a.z, sc.z, sh.z); o0.w = fmaf(a.w, sc.w, sh.w);
        o1.x = fmaf(c.x, sc.x, sh.x); o1.y = fmaf(c.y, sc.y, sh.y);
        o1.z = fmaf(c.z, sc.z, sh.z); o1.w = fmaf(c.w, sc.w, sh.w);
        float4* po_k = po + (size_t)(nch - 1) * 64;
        __stcs(po_k, o0);
        __stcs(po_k + 32, o1);
    }
    if (r + 4 <= rows) {
        float4 a = __ldcs(pi + (size_t)r * 8);
        float4 o;
        o.x = fmaf(a.x, sc.x, sh.x); o.y = fmaf(a.y, sc.y, sh.y);
        o.z = fmaf(a.z, sc.z, sh.z); o.w = fmaf(a.w, sc.w, sh.w);
        __stcs(po + (size_t)r * 8, o);
        r += 4;
    }
    if (r < rows && r + rg < rows) {   // 1-3 remaining rows, predicated
        float4 a = __ldcs(pi + (size_t)r * 8);
        float4 o;
        o.x = fmaf(a.x, sc.x, sh.x); o.y = fmaf(a.y, sc.y, sh.y);
        o.z = fmaf(a.z, sc.z, sh.z); o.w = fmaf(a.w, sc.w, sh.w);
        __stcs(po + (size_t)r * 8, o);
    }
}

// ---------------------------------------------------------------------------
// Kernel 3: normalize, warp-chunked like the reduce.
// ---------------------------------------------------------------------------
__global__ void normalize_kernel(const float* __restrict__ data,
                                 const int* __restrict__ bid,
                                 float* __restrict__ out,
                                 int N, int rows_per_warp) {
    __shared__ float4 s_scale[BMAX * C / 4];
    __shared__ float4 s_shift[BMAX * C / 4];
    for (int i = threadIdx.x; i < BMAX * C / 4; i += blockDim.x) {
        s_scale[i] = reinterpret_cast<const float4*>(g_scale)[i];
        s_shift[i] = reinterpret_cast<const float4*>(g_shift)[i];
    }
    __syncthreads();

    int warp = (int)((blockIdx.x * blockDim.x + threadIdx.x) >> 5);
    int lane = threadIdx.x & 31;

    int r0 = warp * rows_per_warp;
    if (r0 >= N) return;
    int r1 = r0 + rows_per_warp;
    if (r1 > N) r1 = N;

    int b_first = bid[r0];
    int b_last = bid[r1 - 1];

    if (b_first == b_last) {
        norm_run(data, out, s_scale, s_shift, r0, r1, b_first, lane);
    } else {
        int r = r0;
        int b = b_first;
        while (r < r1) {
            int lo = r + 1, hi = r1;
            while (lo < hi) {
                int mid = (lo + hi) >> 1;     // broadcast load
                if (bid[mid] == b) lo = mid + 1;
                else hi = mid;
            }
            norm_run(data, out, s_scale, s_shift, r, lo, b, lane);
            r = lo;
            if (r < r1) b = bid[r];
        }
    }
}

// ---------------------------------------------------------------------------
extern "C" void kernel_launch(void* const* d_in, const int* in_sizes, int n_in,
                              void* d_out, int out_size) {
    const float* data = (const float*)d_in[0];
    const int* bid = (const int*)d_in[1];
    int N = in_sizes[0] / C;

    // Locate weights/bias among the remaining inputs (size-32 fp32 arrays).
    const float* w = nullptr;
    const float* bias = nullptr;
    for (int i = 2; i < n_in; ++i) {
        if (in_sizes[i] == C) {
            if (!w) w = (const float*)d_in[i];
            else if (!bias) bias = (const float*)d_in[i];
        }
    }

    const int threads = 256;

    // Reduce: single wave at 4 blocks/SM.
    {
        const int blocks = 148 * 4;
        int warps = blocks * (threads / 32);
        int rpw = (N + warps - 1) / warps;
        reduce_kernel<<<blocks, threads>>>(data, bid, N, rpw);
    }

    finalize_kernel<<<1, BMAX * C>>>(w, bias);

    // Normalize: single wave at 8 blocks/SM (R10-validated config).
    {
        const int blocks = 148 * 8;
        int warps = blocks * (threads / 32);
        int rpw = (N + warps - 1) / warps;
        normalize_kernel<<<blocks, threads>>>(data, bid, (float*)d_out,
                                              N, rpw);
    }
}